// round 1
// baseline (speedup 1.0000x reference)
#include <cuda_runtime.h>
#include <math.h>

// Problem constants
#define C_CH 8
#define F_DIM 1024
#define W_FR 512
#define H_HEADS 16
#define D_HEAD 64
#define F4 4096

// ---------------------------------------------------------------------------
// Scratch (static __device__ arrays — the sanctioned allocation-free path)
// ---------------------------------------------------------------------------
__device__ float g_z[C_CH * F_DIM * W_FR];                       // 16 MB: normed activations
__device__ float g_p[C_CH * F_DIM * W_FR];                       // 16 MB: q/k/v projection
__device__ float g_o[C_CH * F_DIM * W_FR];                       // 16 MB: attention output
__device__ float g_h[(size_t)C_CH * F4 * W_FR];                  // 64 MB: MLP hidden
__device__ float g_s[(size_t)C_CH * H_HEADS * W_FR * W_FR];      // 134 MB: scores s[head][j][i]

// ---------------------------------------------------------------------------
// Frame norm: LayerNorm over F for each (c, w) column
// grid (C, W/32), block 256 = (32 w-lanes) x (8 f-groups)
// ---------------------------------------------------------------------------
__global__ __launch_bounds__(256) void frame_norm_kernel(
    const float* __restrict__ in, const float* __restrict__ gw,
    const float* __restrict__ bw, float* __restrict__ out)
{
    int c  = blockIdx.x;
    int w0 = blockIdx.y * 32;
    int wx = threadIdx.x & 31;
    int fg = threadIdx.x >> 5;
    const float* base = in + ((size_t)c * F_DIM) * W_FR + w0 + wx;

    float s = 0.f, ss = 0.f;
    for (int f = fg; f < F_DIM; f += 8) {
        float v = base[(size_t)f * W_FR];
        s += v; ss += v * v;
    }
    __shared__ float red[2][8][32];
    __shared__ float smu[32], srs[32];
    red[0][fg][wx] = s; red[1][fg][wx] = ss;
    __syncthreads();
    if (fg == 0) {
        float S = 0.f, SS = 0.f;
#pragma unroll
        for (int i = 0; i < 8; i++) { S += red[0][i][wx]; SS += red[1][i][wx]; }
        float mu  = S * (1.0f / F_DIM);
        float var = SS * (1.0f / F_DIM) - mu * mu;
        smu[wx] = mu;
        srs[wx] = rsqrtf(var + 1e-5f);
    }
    __syncthreads();
    float mu = smu[wx], rs = srs[wx];
    float* ob = out + ((size_t)c * F_DIM) * W_FR + w0 + wx;
    for (int f = fg; f < F_DIM; f += 8) {
        float v = base[(size_t)f * W_FR];
        ob[(size_t)f * W_FR] = (v - mu) * rs * gw[f] + bw[f];
    }
}

// ---------------------------------------------------------------------------
// Batched SGEMM: C[c] (+= / gelu) = A[c] (MxK row-major) * B[c] (KxN row-major)
// N = 512 fixed. BM=BN=128, BK=8, 256 threads, 8x8 per thread (split 4+4).
// epi: 0 = store, 1 = exact GELU then store, 2 = add residual then store
// ---------------------------------------------------------------------------
#define BM 128
#define BN 128
#define BK 8

__global__ __launch_bounds__(256) void sgemm_kernel(
    const float* __restrict__ A, const float* __restrict__ B,
    float* __restrict__ Cm, const float* __restrict__ R,
    int M, int K, int epi)
{
    const int N = W_FR;
    int c  = blockIdx.z;
    int bm = blockIdx.y * BM;
    int bn = blockIdx.x * BN;
    A  += (size_t)c * M * K;
    B  += (size_t)c * K * N;
    Cm += (size_t)c * M * N;
    if (R) R += (size_t)c * M * N;

    __shared__ float As[BK][BM];
    __shared__ float Bs[BK][BN];

    int tid  = threadIdx.x;
    int arow = tid >> 1;
    int acol = (tid & 1) * 4;
    int brow = tid >> 5;
    int bcol = (tid & 31) * 4;
    int ty   = tid >> 4;   // 0..15
    int tx   = tid & 15;   // 0..15

    float acc[8][8];
#pragma unroll
    for (int i = 0; i < 8; i++)
#pragma unroll
        for (int j = 0; j < 8; j++) acc[i][j] = 0.f;

    const float* Ap = A + (size_t)(bm + arow) * K + acol;
    const float* Bp = B + (size_t)brow * N + bn + bcol;

    for (int k0 = 0; k0 < K; k0 += BK) {
        float4 av = *(const float4*)Ap;
        float4 bv = *(const float4*)Bp;
        As[acol + 0][arow] = av.x;
        As[acol + 1][arow] = av.y;
        As[acol + 2][arow] = av.z;
        As[acol + 3][arow] = av.w;
        *(float4*)&Bs[brow][bcol] = bv;
        __syncthreads();
#pragma unroll
        for (int k = 0; k < BK; k++) {
            float a[8], b[8];
            *(float4*)&a[0] = *(const float4*)&As[k][ty * 4];
            *(float4*)&a[4] = *(const float4*)&As[k][64 + ty * 4];
            *(float4*)&b[0] = *(const float4*)&Bs[k][tx * 4];
            *(float4*)&b[4] = *(const float4*)&Bs[k][64 + tx * 4];
#pragma unroll
            for (int i = 0; i < 8; i++)
#pragma unroll
                for (int j = 0; j < 8; j++)
                    acc[i][j] += a[i] * b[j];
        }
        __syncthreads();
        Ap += BK;
        Bp += (size_t)BK * N;
    }

#pragma unroll
    for (int i = 0; i < 8; i++) {
        int r = bm + ((i < 4) ? (ty * 4 + i) : (64 + ty * 4 + (i - 4)));
        size_t rowoff = (size_t)r * N + bn;
#pragma unroll
        for (int half = 0; half < 2; half++) {
            int cc = half * 64 + tx * 4;
            float4 v;
            v.x = acc[i][half * 4 + 0];
            v.y = acc[i][half * 4 + 1];
            v.z = acc[i][half * 4 + 2];
            v.w = acc[i][half * 4 + 3];
            if (epi == 1) {
                v.x = 0.5f * v.x * (1.f + erff(v.x * 0.70710678118654752f));
                v.y = 0.5f * v.y * (1.f + erff(v.y * 0.70710678118654752f));
                v.z = 0.5f * v.z * (1.f + erff(v.z * 0.70710678118654752f));
                v.w = 0.5f * v.w * (1.f + erff(v.w * 0.70710678118654752f));
            } else if (epi == 2) {
                float4 rv = *(const float4*)(R + rowoff + cc);
                v.x += rv.x; v.y += rv.y; v.z += rv.z; v.w += rv.w;
            }
            *(float4*)(Cm + rowoff + cc) = v;
        }
    }
}

// ---------------------------------------------------------------------------
// Attention: one block per (c, h). 512 threads = 512 queries.
// p slab is (D=64 rows) x (W=512 cols) of the projection (d, w) layout.
// q == k == rope(t); v == t (v differs from q only in first 32 dims).
// Two-pass softmax: pass1 computes scores + (m, l) and spills scores to
// global (transposed for coalescing); pass2 accumulates o.
// ---------------------------------------------------------------------------
#define QS 68   // padded stride for q smem rows (conflict-free float4)
#define VS 36   // padded stride for v-rot smem rows

__global__ __launch_bounds__(512) void attention_kernel(
    const float* __restrict__ p, const float* __restrict__ freqs,
    float* __restrict__ o, float* __restrict__ sbuf)
{
    extern __shared__ float smem[];
    float* qs = smem;               // [512][QS]  roped q (= k); d>=32 also = v
    float* vs = smem + 512 * QS;    // [512][VS]  un-roped first 32 dims (= v)

    int head = blockIdx.x;          // 0..127
    int c = head >> 4;
    int h = head & 15;
    const float* slab = p + ((size_t)c * F_DIM + (size_t)h * D_HEAD) * W_FR;
    int w = threadIdx.x;
    float fw = (float)w;

#pragma unroll
    for (int i = 0; i < 16; i++) {
        float e0 = slab[(size_t)(2 * i) * W_FR + w];
        float e1 = slab[(size_t)(2 * i + 1) * W_FR + w];
        float si, co;
        sincosf(fw * freqs[i], &si, &co);   // accurate range reduction (args up to ~8e3)
        qs[w * QS + 2 * i]     = e0 * co - e1 * si;
        qs[w * QS + 2 * i + 1] = e1 * co + e0 * si;
        vs[w * VS + 2 * i]     = e0;
        vs[w * VS + 2 * i + 1] = e1;
    }
#pragma unroll
    for (int d = 32; d < 64; d++)
        qs[w * QS + d] = slab[(size_t)d * W_FR + w];
    __syncthreads();

    float* srow = sbuf + (size_t)head * W_FR * W_FR;   // s[j][i] (transposed)
    const float scale = 0.03125f;   // 1/sqrt(F) = 1/32

    // ---- pass 1: scores + online (m, l) ----
    float qi[64];
#pragma unroll
    for (int d = 0; d < 64; d += 4)
        *(float4*)&qi[d] = *(const float4*)&qs[w * QS + d];

    float m = -1e30f, l = 0.f;
    for (int j = 0; j < 512; j++) {
        const float* qj = &qs[j * QS];
        float s = 0.f;
#pragma unroll
        for (int d = 0; d < 64; d += 4) {
            float4 q4 = *(const float4*)&qj[d];
            s += qi[d] * q4.x + qi[d + 1] * q4.y + qi[d + 2] * q4.z + qi[d + 3] * q4.w;
        }
        s *= scale;
        srow[(size_t)j * W_FR + w] = s;
        float mn = fmaxf(m, s);
        l = l * __expf(m - mn) + __expf(s - mn);
        m = mn;
    }
    float linv = 1.f / l;

    // ---- pass 2: o = softmax(s) @ v ----
    float oa[64];
#pragma unroll
    for (int d = 0; d < 64; d++) oa[d] = 0.f;

    for (int j = 0; j < 512; j++) {
        float pij = __expf(srow[(size_t)j * W_FR + w] - m) * linv;
        const float* vj = &vs[j * VS];
        const float* qj = &qs[j * QS];
#pragma unroll
        for (int d = 0; d < 32; d += 4) {
            float4 v4 = *(const float4*)&vj[d];
            oa[d]     += pij * v4.x;
            oa[d + 1] += pij * v4.y;
            oa[d + 2] += pij * v4.z;
            oa[d + 3] += pij * v4.w;
        }
#pragma unroll
        for (int d = 32; d < 64; d += 4) {
            float4 v4 = *(const float4*)&qj[d];   // v == q (= t) for d >= 32
            oa[d]     += pij * v4.x;
            oa[d + 1] += pij * v4.y;
            oa[d + 2] += pij * v4.z;
            oa[d + 3] += pij * v4.w;
        }
    }

    float* ob = o + ((size_t)c * F_DIM + (size_t)h * D_HEAD) * W_FR + w;
#pragma unroll
    for (int d = 0; d < 64; d++)
        ob[(size_t)d * W_FR] = oa[d];
}

// ---------------------------------------------------------------------------
// Launch
// ---------------------------------------------------------------------------
extern "C" void kernel_launch(void* const* d_in, const int* in_sizes, int n_in,
                              void* d_out, int out_size)
{
    (void)in_sizes; (void)n_in; (void)out_size;
    const float* x  = (const float*)d_in[0];
    const float* g1 = (const float*)d_in[1];
    const float* b1 = (const float*)d_in[2];
    const float* wq = (const float*)d_in[3];
    const float* wo = (const float*)d_in[4];
    const float* fr = (const float*)d_in[5];
    const float* g2 = (const float*)d_in[6];
    const float* b2 = (const float*)d_in[7];
    const float* w1 = (const float*)d_in[8];
    const float* w2 = (const float*)d_in[9];
    float* out = (float*)d_out;

    float *z, *p, *o, *h, *s;
    cudaGetSymbolAddress((void**)&z, g_z);
    cudaGetSymbolAddress((void**)&p, g_p);
    cudaGetSymbolAddress((void**)&o, g_o);
    cudaGetSymbolAddress((void**)&h, g_h);
    cudaGetSymbolAddress((void**)&s, g_s);

    int smem_attn = 512 * (QS + VS) * (int)sizeof(float);   // 212,992 B
    cudaFuncSetAttribute(attention_kernel,
                         cudaFuncAttributeMaxDynamicSharedMemorySize, smem_attn);

    // z = frame_norm(x)
    frame_norm_kernel<<<dim3(8, 16), 256>>>(x, g1, b1, z);
    // p = w_q @ z
    sgemm_kernel<<<dim3(4, 8, 8), 256>>>(wq, z, p, nullptr, F_DIM, F_DIM, 0);
    // o = attention(p)
    attention_kernel<<<128, 512, smem_attn>>>(p, fr, o, s);
    // x2 = x + w_o @ o   -> d_out
    sgemm_kernel<<<dim3(4, 8, 8), 256>>>(wo, o, out, x, F_DIM, F_DIM, 2);
    // z2 = frame_norm(x2)
    frame_norm_kernel<<<dim3(8, 16), 256>>>(out, g2, b2, z);
    // hgelu = gelu(w1 @ z2)
    sgemm_kernel<<<dim3(4, 32, 8), 256>>>(w1, z, h, nullptr, F4, F_DIM, 1);
    // out = x2 + w2 @ hgelu
    sgemm_kernel<<<dim3(4, 8, 8), 256>>>(w2, h, out, out, F_DIM, F4, 2);
}

// round 2
// speedup vs baseline: 1.9285x; 1.9285x over previous
#include <cuda_runtime.h>
#include <math.h>
#include <stdint.h>

// Problem constants
#define C_CH 8
#define F_DIM 1024
#define W_FR 512
#define H_HEADS 16
#define D_HEAD 64
#define F4 4096

// ---------------------------------------------------------------------------
// Scratch (static __device__ arrays — the sanctioned allocation-free path)
// ---------------------------------------------------------------------------
__device__ float g_z[C_CH * F_DIM * W_FR];                       // 16 MB
__device__ float g_p[C_CH * F_DIM * W_FR];                       // 16 MB
__device__ float g_o[C_CH * F_DIM * W_FR];                       // 16 MB
__device__ float g_h[(size_t)C_CH * F4 * W_FR];                  // 64 MB
__device__ float g_s[(size_t)C_CH * H_HEADS * W_FR * W_FR];      // 134 MB

// ---------------------------------------------------------------------------
// Frame norm
// ---------------------------------------------------------------------------
__global__ __launch_bounds__(256) void frame_norm_kernel(
    const float* __restrict__ in, const float* __restrict__ gw,
    const float* __restrict__ bw, float* __restrict__ out)
{
    int c  = blockIdx.x;
    int w0 = blockIdx.y * 32;
    int wx = threadIdx.x & 31;
    int fg = threadIdx.x >> 5;
    const float* base = in + ((size_t)c * F_DIM) * W_FR + w0 + wx;

    float s = 0.f, ss = 0.f;
    for (int f = fg; f < F_DIM; f += 8) {
        float v = base[(size_t)f * W_FR];
        s += v; ss += v * v;
    }
    __shared__ float red[2][8][32];
    __shared__ float smu[32], srs[32];
    red[0][fg][wx] = s; red[1][fg][wx] = ss;
    __syncthreads();
    if (fg == 0) {
        float S = 0.f, SS = 0.f;
#pragma unroll
        for (int i = 0; i < 8; i++) { S += red[0][i][wx]; SS += red[1][i][wx]; }
        float mu  = S * (1.0f / F_DIM);
        float var = SS * (1.0f / F_DIM) - mu * mu;
        smu[wx] = mu;
        srs[wx] = rsqrtf(var + 1e-5f);
    }
    __syncthreads();
    float mu = smu[wx], rs = srs[wx];
    float* ob = out + ((size_t)c * F_DIM) * W_FR + w0 + wx;
    for (int f = fg; f < F_DIM; f += 8) {
        float v = base[(size_t)f * W_FR];
        ob[(size_t)f * W_FR] = (v - mu) * rs * gw[f] + bw[f];
    }
}

// ---------------------------------------------------------------------------
// TF32 tensor-core batched GEMM
// C[c] = A[c] (MxK row-major) * B[c] (KxN row-major), N = 512.
// BM=BN=128, BK=16, 256 threads = 8 warps (2m x 4n), warp tile 64x32.
// mma.sync.m16n8k8.tf32; inputs rounded to tf32 (RN) at the smem-store stage.
// epi: 0 = store, 1 = exact GELU, 2 = add residual R
// ---------------------------------------------------------------------------
#define BM 128
#define BN 128
#define BK 16
#define SPAD 136   // smem row stride in words: bank = (8k+g)%32, conflict-free frags

__device__ __forceinline__ uint32_t f2tf32(float x) {
    uint32_t y;
    asm("cvt.rna.tf32.f32 %0, %1;" : "=r"(y) : "f"(x));
    return y;
}

__device__ __forceinline__ void mma_tf32(float* c, const uint32_t* a, const uint32_t* b) {
    asm volatile(
        "mma.sync.aligned.m16n8k8.row.col.f32.tf32.tf32.f32 "
        "{%0,%1,%2,%3}, {%4,%5,%6,%7}, {%8,%9}, {%0,%1,%2,%3};"
        : "+f"(c[0]), "+f"(c[1]), "+f"(c[2]), "+f"(c[3])
        : "r"(a[0]), "r"(a[1]), "r"(a[2]), "r"(a[3]), "r"(b[0]), "r"(b[1]));
}

__global__ __launch_bounds__(256) void tgemm_kernel(
    const float* __restrict__ A, const float* __restrict__ B,
    float* __restrict__ Cm, const float* __restrict__ R,
    int M, int K, int epi)
{
    const int N = W_FR;
    int c  = blockIdx.z;
    int bm = blockIdx.y * BM;
    int bn = blockIdx.x * BN;
    A  += (size_t)c * M * K;
    B  += (size_t)c * K * N;
    Cm += (size_t)c * M * N;
    if (R) R += (size_t)c * M * N;

    __shared__ uint32_t As[2][BK][SPAD];   // As[k][m] (transposed), tf32 bits
    __shared__ uint32_t Bs[2][BK][SPAD];   // Bs[k][n], tf32 bits

    int tid  = threadIdx.x;
    int warp = tid >> 5;
    int lane = tid & 31;
    int gid  = lane >> 2;      // 0..7
    int tig  = lane & 3;       // 0..3
    int wm   = warp >> 2;      // 0..1
    int wn   = warp & 3;       // 0..3

    // global-load assignments
    int am = tid >> 1;             // 0..127 (A row within tile)
    int ak = (tid & 1) * 8;        // 0 or 8 (k offset; loads k..k+7 as 2 float4)
    int bk = tid >> 4;             // 0..15  (B k-row within tile)
    int bn0 = (tid & 15) * 4;      // 0..60  (B n offset; second chunk at +64)

    const float* Ap = A + (size_t)(bm + am) * K + ak;
    const float* Bp = B + (size_t)bk * N + bn + bn0;

    float ar[8], br[8];
    // prologue: tile 0
    *(float4*)&ar[0] = *(const float4*)(Ap + 0);
    *(float4*)&ar[4] = *(const float4*)(Ap + 4);
    *(float4*)&br[0] = *(const float4*)(Bp + 0);
    *(float4*)&br[4] = *(const float4*)(Bp + 64);
#pragma unroll
    for (int j = 0; j < 8; j++) As[0][ak + j][am] = f2tf32(ar[j]);
#pragma unroll
    for (int j = 0; j < 4; j++) { Bs[0][bk][bn0 + j] = f2tf32(br[j]); Bs[0][bk][bn0 + 64 + j] = f2tf32(br[4 + j]); }
    __syncthreads();

    float acc[4][4][4];
#pragma unroll
    for (int i = 0; i < 4; i++)
#pragma unroll
        for (int j = 0; j < 4; j++)
#pragma unroll
            for (int q = 0; q < 4; q++) acc[i][j][q] = 0.f;

    const int NTILES = K / BK;
    for (int t = 0; t < NTILES; t++) {
        int cur = t & 1;
        if (t + 1 < NTILES) {
            const float* Ap2 = Ap + (size_t)(t + 1) * BK;
            const float* Bp2 = Bp + (size_t)(t + 1) * BK * N;
            *(float4*)&ar[0] = *(const float4*)(Ap2 + 0);
            *(float4*)&ar[4] = *(const float4*)(Ap2 + 4);
            *(float4*)&br[0] = *(const float4*)(Bp2 + 0);
            *(float4*)&br[4] = *(const float4*)(Bp2 + 64);
        }
#pragma unroll
        for (int kk = 0; kk < 2; kk++) {
            int kb = kk * 8;
            uint32_t af[4][4], bf[4][2];
#pragma unroll
            for (int mt = 0; mt < 4; mt++) {
                int mb = wm * 64 + mt * 16 + gid;
                af[mt][0] = As[cur][kb + tig][mb];
                af[mt][1] = As[cur][kb + tig][mb + 8];
                af[mt][2] = As[cur][kb + tig + 4][mb];
                af[mt][3] = As[cur][kb + tig + 4][mb + 8];
            }
#pragma unroll
            for (int nt = 0; nt < 4; nt++) {
                int nb = wn * 32 + nt * 8 + gid;
                bf[nt][0] = Bs[cur][kb + tig][nb];
                bf[nt][1] = Bs[cur][kb + tig + 4][nb];
            }
#pragma unroll
            for (int mt = 0; mt < 4; mt++)
#pragma unroll
                for (int nt = 0; nt < 4; nt++)
                    mma_tf32(acc[mt][nt], af[mt], bf[nt]);
        }
        if (t + 1 < NTILES) {
            int nxt = cur ^ 1;
#pragma unroll
            for (int j = 0; j < 8; j++) As[nxt][ak + j][am] = f2tf32(ar[j]);
#pragma unroll
            for (int j = 0; j < 4; j++) { Bs[nxt][bk][bn0 + j] = f2tf32(br[j]); Bs[nxt][bk][bn0 + 64 + j] = f2tf32(br[4 + j]); }
            __syncthreads();
        }
    }

    // epilogue
#pragma unroll
    for (int mt = 0; mt < 4; mt++) {
#pragma unroll
        for (int nt = 0; nt < 4; nt++) {
            int row0 = bm + wm * 64 + mt * 16 + gid;
            int col  = bn + wn * 32 + nt * 8 + 2 * tig;
#pragma unroll
            for (int half = 0; half < 2; half++) {
                int row = row0 + half * 8;
                float2 v = make_float2(acc[mt][nt][half * 2], acc[mt][nt][half * 2 + 1]);
                size_t off = (size_t)row * N + col;
                if (epi == 1) {
                    v.x = 0.5f * v.x * (1.f + erff(v.x * 0.70710678118654752f));
                    v.y = 0.5f * v.y * (1.f + erff(v.y * 0.70710678118654752f));
                } else if (epi == 2) {
                    float2 rv = *(const float2*)(R + off);
                    v.x += rv.x; v.y += rv.y;
                }
                *(float2*)(Cm + off) = v;
            }
        }
    }
}

// ---------------------------------------------------------------------------
// Attention: one block per (c, h). 512 threads = 512 queries. (unchanged)
// ---------------------------------------------------------------------------
#define QS 68
#define VS 36

__global__ __launch_bounds__(512) void attention_kernel(
    const float* __restrict__ p, const float* __restrict__ freqs,
    float* __restrict__ o, float* __restrict__ sbuf)
{
    extern __shared__ float smem[];
    float* qs = smem;               // [512][QS]  roped q (= k); d>=32 also = v
    float* vs = smem + 512 * QS;    // [512][VS]  un-roped first 32 dims (= v)

    int head = blockIdx.x;
    int c = head >> 4;
    int h = head & 15;
    const float* slab = p + ((size_t)c * F_DIM + (size_t)h * D_HEAD) * W_FR;
    int w = threadIdx.x;
    float fw = (float)w;

#pragma unroll
    for (int i = 0; i < 16; i++) {
        float e0 = slab[(size_t)(2 * i) * W_FR + w];
        float e1 = slab[(size_t)(2 * i + 1) * W_FR + w];
        float si, co;
        sincosf(fw * freqs[i], &si, &co);
        qs[w * QS + 2 * i]     = e0 * co - e1 * si;
        qs[w * QS + 2 * i + 1] = e1 * co + e0 * si;
        vs[w * VS + 2 * i]     = e0;
        vs[w * VS + 2 * i + 1] = e1;
    }
#pragma unroll
    for (int d = 32; d < 64; d++)
        qs[w * QS + d] = slab[(size_t)d * W_FR + w];
    __syncthreads();

    float* srow = sbuf + (size_t)head * W_FR * W_FR;
    const float scale = 0.03125f;

    float qi[64];
#pragma unroll
    for (int d = 0; d < 64; d += 4)
        *(float4*)&qi[d] = *(const float4*)&qs[w * QS + d];

    float m = -1e30f, l = 0.f;
    for (int j = 0; j < 512; j++) {
        const float* qj = &qs[j * QS];
        float s = 0.f;
#pragma unroll
        for (int d = 0; d < 64; d += 4) {
            float4 q4 = *(const float4*)&qj[d];
            s += qi[d] * q4.x + qi[d + 1] * q4.y + qi[d + 2] * q4.z + qi[d + 3] * q4.w;
        }
        s *= scale;
        srow[(size_t)j * W_FR + w] = s;
        float mn = fmaxf(m, s);
        l = l * __expf(m - mn) + __expf(s - mn);
        m = mn;
    }
    float linv = 1.f / l;

    float oa[64];
#pragma unroll
    for (int d = 0; d < 64; d++) oa[d] = 0.f;

    for (int j = 0; j < 512; j++) {
        float pij = __expf(srow[(size_t)j * W_FR + w] - m) * linv;
        const float* vj = &vs[j * VS];
        const float* qj = &qs[j * QS];
#pragma unroll
        for (int d = 0; d < 32; d += 4) {
            float4 v4 = *(const float4*)&vj[d];
            oa[d]     += pij * v4.x;
            oa[d + 1] += pij * v4.y;
            oa[d + 2] += pij * v4.z;
            oa[d + 3] += pij * v4.w;
        }
#pragma unroll
        for (int d = 32; d < 64; d += 4) {
            float4 v4 = *(const float4*)&qj[d];
            oa[d]     += pij * v4.x;
            oa[d + 1] += pij * v4.y;
            oa[d + 2] += pij * v4.z;
            oa[d + 3] += pij * v4.w;
        }
    }

    float* ob = o + ((size_t)c * F_DIM + (size_t)h * D_HEAD) * W_FR + w;
#pragma unroll
    for (int d = 0; d < 64; d++)
        ob[(size_t)d * W_FR] = oa[d];
}

// ---------------------------------------------------------------------------
// Launch
// ---------------------------------------------------------------------------
extern "C" void kernel_launch(void* const* d_in, const int* in_sizes, int n_in,
                              void* d_out, int out_size)
{
    (void)in_sizes; (void)n_in; (void)out_size;
    const float* x  = (const float*)d_in[0];
    const float* g1 = (const float*)d_in[1];
    const float* b1 = (const float*)d_in[2];
    const float* wq = (const float*)d_in[3];
    const float* wo = (const float*)d_in[4];
    const float* fr = (const float*)d_in[5];
    const float* g2 = (const float*)d_in[6];
    const float* b2 = (const float*)d_in[7];
    const float* w1 = (const float*)d_in[8];
    const float* w2 = (const float*)d_in[9];
    float* out = (float*)d_out;

    float *z, *p, *o, *h, *s;
    cudaGetSymbolAddress((void**)&z, g_z);
    cudaGetSymbolAddress((void**)&p, g_p);
    cudaGetSymbolAddress((void**)&o, g_o);
    cudaGetSymbolAddress((void**)&h, g_h);
    cudaGetSymbolAddress((void**)&s, g_s);

    int smem_attn = 512 * (QS + VS) * (int)sizeof(float);
    cudaFuncSetAttribute(attention_kernel,
                         cudaFuncAttributeMaxDynamicSharedMemorySize, smem_attn);

    // z = frame_norm(x)
    frame_norm_kernel<<<dim3(8, 16), 256>>>(x, g1, b1, z);
    // p = w_q @ z
    tgemm_kernel<<<dim3(4, 8, 8), 256>>>(wq, z, p, nullptr, F_DIM, F_DIM, 0);
    // o = attention(p)
    attention_kernel<<<128, 512, smem_attn>>>(p, fr, o, s);
    // x2 = x + w_o @ o   -> d_out
    tgemm_kernel<<<dim3(4, 8, 8), 256>>>(wo, o, out, x, F_DIM, F_DIM, 2);
    // z2 = frame_norm(x2)
    frame_norm_kernel<<<dim3(8, 16), 256>>>(out, g2, b2, z);
    // hgelu = gelu(w1 @ z2)
    tgemm_kernel<<<dim3(4, 32, 8), 256>>>(w1, z, h, nullptr, F4, F_DIM, 1);
    // out = x2 + w2 @ hgelu
    tgemm_kernel<<<dim3(4, 8, 8), 256>>>(w2, h, out, out, F_DIM, F4, 2);
}

// round 4
// speedup vs baseline: 2.0415x; 1.0586x over previous
#include <cuda_runtime.h>
#include <math.h>
#include <stdint.h>

// Problem constants
#define C_CH 8
#define F_DIM 1024
#define W_FR 512
#define H_HEADS 16
#define D_HEAD 64
#define F4 4096

// ---------------------------------------------------------------------------
// Scratch
// ---------------------------------------------------------------------------
__device__ float g_z[C_CH * F_DIM * W_FR];                       // 16 MB
__device__ float g_p[C_CH * F_DIM * W_FR];                       // 16 MB
__device__ float g_o[C_CH * F_DIM * W_FR];                       // 16 MB
__device__ float g_h[(size_t)C_CH * F4 * W_FR];                  // 64 MB
__device__ float g_s[(size_t)C_CH * H_HEADS * W_FR * W_FR];      // 134 MB

// ---------------------------------------------------------------------------
// Frame norm
// ---------------------------------------------------------------------------
__global__ __launch_bounds__(256) void frame_norm_kernel(
    const float* __restrict__ in, const float* __restrict__ gw,
    const float* __restrict__ bw, float* __restrict__ out)
{
    int c  = blockIdx.x;
    int w0 = blockIdx.y * 32;
    int wx = threadIdx.x & 31;
    int fg = threadIdx.x >> 5;
    const float* base = in + ((size_t)c * F_DIM) * W_FR + w0 + wx;

    float s = 0.f, ss = 0.f;
    for (int f = fg; f < F_DIM; f += 8) {
        float v = base[(size_t)f * W_FR];
        s += v; ss += v * v;
    }
    __shared__ float red[2][8][32];
    __shared__ float smu[32], srs[32];
    red[0][fg][wx] = s; red[1][fg][wx] = ss;
    __syncthreads();
    if (fg == 0) {
        float S = 0.f, SS = 0.f;
#pragma unroll
        for (int i = 0; i < 8; i++) { S += red[0][i][wx]; SS += red[1][i][wx]; }
        float mu  = S * (1.0f / F_DIM);
        float var = SS * (1.0f / F_DIM) - mu * mu;
        smu[wx] = mu;
        srs[wx] = rsqrtf(var + 1e-5f);
    }
    __syncthreads();
    float mu = smu[wx], rs = srs[wx];
    float* ob = out + ((size_t)c * F_DIM) * W_FR + w0 + wx;
    for (int f = fg; f < F_DIM; f += 8) {
        float v = base[(size_t)f * W_FR];
        ob[(size_t)f * W_FR] = (v - mu) * rs * gw[f] + bw[f];
    }
}

// ---------------------------------------------------------------------------
// TF32 tensor-core batched GEMM, cp.async 3-stage pipeline, 2 CTAs/SM.
// C[c] = A[c] (MxK rm) * B[c] (KxN rm), N = 512. BM=BN=128, BK=16.
// 256 threads = 8 warps (2m x 4n), warp tile 64x32, mma m16n8k8.
// fp32 bits fed directly as tf32 (RZ truncation).
// Smem is DYNAMIC (56,064 B > 48 KB static cap).
// epi: 0 = store, 1 = exact GELU, 2 = add residual R
// ---------------------------------------------------------------------------
#define BM 128
#define BN 128
#define BK 16
#define STAGES 3
#define AKP 20    // As row pad: bank=(20g+tig)%32 bijective
#define BNP 132   // Bs row pad: bank=(4tig+g)%32 bijective

#define A_STAGE_W (BM * AKP)                 // 2560 words
#define B_STAGE_W (BK * BNP)                 // 2112 words
#define GEMM_SMEM_BYTES ((STAGES * (A_STAGE_W + B_STAGE_W)) * 4)   // 56,064

__device__ __forceinline__ void cp16(void* dst, const void* src) {
    uint32_t d = (uint32_t)__cvta_generic_to_shared(dst);
    asm volatile("cp.async.ca.shared.global [%0], [%1], 16;" :: "r"(d), "l"(src));
}

__device__ __forceinline__ void mma_tf32(float* c, const uint32_t* a, const uint32_t* b) {
    asm volatile(
        "mma.sync.aligned.m16n8k8.row.col.f32.tf32.tf32.f32 "
        "{%0,%1,%2,%3}, {%4,%5,%6,%7}, {%8,%9}, {%0,%1,%2,%3};"
        : "+f"(c[0]), "+f"(c[1]), "+f"(c[2]), "+f"(c[3])
        : "r"(a[0]), "r"(a[1]), "r"(a[2]), "r"(a[3]), "r"(b[0]), "r"(b[1]));
}

__global__ __launch_bounds__(256, 2) void tgemm_kernel(
    const float* __restrict__ A, const float* __restrict__ B,
    float* __restrict__ Cm, const float* __restrict__ R,
    int M, int K, int epi)
{
    const int N = W_FR;
    int c  = blockIdx.z;
    int bm = blockIdx.y * BM;
    int bn = blockIdx.x * BN;
    A  += (size_t)c * M * K;
    B  += (size_t)c * K * N;
    Cm += (size_t)c * M * N;
    if (R) R += (size_t)c * M * N;

    extern __shared__ float smem[];
    float* Asm = smem;                          // [STAGES][BM][AKP]
    float* Bsm = smem + STAGES * A_STAGE_W;     // [STAGES][BK][BNP]
#define AS(s, m, k) Asm[(s) * A_STAGE_W + (m) * AKP + (k)]
#define BS(s, k, n) Bsm[(s) * B_STAGE_W + (k) * BNP + (n)]

    int tid  = threadIdx.x;
    int warp = tid >> 5;
    int lane = tid & 31;
    int gid  = lane >> 2;
    int tig  = lane & 3;
    int wm   = warp >> 2;
    int wn   = warp & 3;

    // copy assignments
    int am = tid >> 1;             // A row 0..127
    int ak = (tid & 1) * 8;        // A k offset 0/8 (2x16B)
    int bk = tid >> 4;             // B k row 0..15
    int bc = (tid & 15) * 8;       // B n offset (2x16B)

    const float* Abase = A + (size_t)(bm + am) * K + ak;
    const float* Bbase = B + (size_t)bk * N + bn + bc;

    const int NTILES = K / BK;

    // prologue: issue stages 0..STAGES-2
#pragma unroll
    for (int s = 0; s < STAGES - 1; s++) {
        const float* Ap = Abase + s * BK;
        const float* Bp = Bbase + (size_t)s * BK * N;
        cp16(&AS(s, am, ak), Ap);
        cp16(&AS(s, am, ak + 4), Ap + 4);
        cp16(&BS(s, bk, bc), Bp);
        cp16(&BS(s, bk, bc + 4), Bp + 4);
        asm volatile("cp.async.commit_group;");
    }

    float acc[4][4][4];
#pragma unroll
    for (int i = 0; i < 4; i++)
#pragma unroll
        for (int j = 0; j < 4; j++)
#pragma unroll
            for (int q = 0; q < 4; q++) acc[i][j][q] = 0.f;

    for (int t = 0; t < NTILES; t++) {
        int cur = t % STAGES;
        asm volatile("cp.async.wait_group %0;" :: "n"(STAGES - 2));
        __syncthreads();

#pragma unroll
        for (int kk = 0; kk < 2; kk++) {
            int kb = kk * 8;
            uint32_t af[4][4], bf[4][2];
#pragma unroll
            for (int mt = 0; mt < 4; mt++) {
                int mb = wm * 64 + mt * 16 + gid;
                af[mt][0] = __float_as_uint(AS(cur, mb, kb + tig));
                af[mt][1] = __float_as_uint(AS(cur, mb + 8, kb + tig));
                af[mt][2] = __float_as_uint(AS(cur, mb, kb + tig + 4));
                af[mt][3] = __float_as_uint(AS(cur, mb + 8, kb + tig + 4));
            }
#pragma unroll
            for (int nt = 0; nt < 4; nt++) {
                int nb = wn * 32 + nt * 8 + gid;
                bf[nt][0] = __float_as_uint(BS(cur, kb + tig, nb));
                bf[nt][1] = __float_as_uint(BS(cur, kb + tig + 4, nb));
            }
#pragma unroll
            for (int mt = 0; mt < 4; mt++)
#pragma unroll
                for (int nt = 0; nt < 4; nt++)
                    mma_tf32(acc[mt][nt], af[mt], bf[nt]);
        }

        // issue tile t+STAGES-1 (syncthreads above guarantees the target stage
        // is no longer being read)
        int tn = t + STAGES - 1;
        if (tn < NTILES) {
            int s = tn % STAGES;
            const float* Ap = Abase + (size_t)tn * BK;
            const float* Bp = Bbase + (size_t)tn * BK * N;
            cp16(&AS(s, am, ak), Ap);
            cp16(&AS(s, am, ak + 4), Ap + 4);
            cp16(&BS(s, bk, bc), Bp);
            cp16(&BS(s, bk, bc + 4), Bp + 4);
        }
        asm volatile("cp.async.commit_group;");
    }

    // epilogue
#pragma unroll
    for (int mt = 0; mt < 4; mt++) {
#pragma unroll
        for (int nt = 0; nt < 4; nt++) {
            int row0 = bm + wm * 64 + mt * 16 + gid;
            int col  = bn + wn * 32 + nt * 8 + 2 * tig;
#pragma unroll
            for (int half = 0; half < 2; half++) {
                int row = row0 + half * 8;
                float2 v = make_float2(acc[mt][nt][half * 2], acc[mt][nt][half * 2 + 1]);
                size_t off = (size_t)row * N + col;
                if (epi == 1) {
                    v.x = 0.5f * v.x * (1.f + erff(v.x * 0.70710678118654752f));
                    v.y = 0.5f * v.y * (1.f + erff(v.y * 0.70710678118654752f));
                } else if (epi == 2) {
                    float2 rv = *(const float2*)(R + off);
                    v.x += rv.x; v.y += rv.y;
                }
                *(float2*)(Cm + off) = v;
            }
        }
    }
#undef AS
#undef BS
}

// ---------------------------------------------------------------------------
// Attention: one block per (c, h). 512 threads = 512 queries.
// ---------------------------------------------------------------------------
#define QS 68
#define VS 36

__global__ __launch_bounds__(512) void attention_kernel(
    const float* __restrict__ p, const float* __restrict__ freqs,
    float* __restrict__ o, float* __restrict__ sbuf)
{
    extern __shared__ float smem[];
    float* qs = smem;               // [512][QS]  roped q (= k); d>=32 also = v
    float* vs = smem + 512 * QS;    // [512][VS]  un-roped first 32 dims (= v)

    int head = blockIdx.x;
    int c = head >> 4;
    int h = head & 15;
    const float* slab = p + ((size_t)c * F_DIM + (size_t)h * D_HEAD) * W_FR;
    int w = threadIdx.x;
    float fw = (float)w;

#pragma unroll
    for (int i = 0; i < 16; i++) {
        float e0 = slab[(size_t)(2 * i) * W_FR + w];
        float e1 = slab[(size_t)(2 * i + 1) * W_FR + w];
        float si, co;
        sincosf(fw * freqs[i], &si, &co);
        qs[w * QS + 2 * i]     = e0 * co - e1 * si;
        qs[w * QS + 2 * i + 1] = e1 * co + e0 * si;
        vs[w * VS + 2 * i]     = e0;
        vs[w * VS + 2 * i + 1] = e1;
    }
#pragma unroll
    for (int d = 32; d < 64; d++)
        qs[w * QS + d] = slab[(size_t)d * W_FR + w];
    __syncthreads();

    float* srow = sbuf + (size_t)head * W_FR * W_FR;
    const float scale = 0.03125f;

    float qi[64];
#pragma unroll
    for (int d = 0; d < 64; d += 4)
        *(float4*)&qi[d] = *(const float4*)&qs[w * QS + d];

    float m = -1e30f, l = 0.f;
    for (int j = 0; j < 512; j++) {
        const float* qj = &qs[j * QS];
        float s0 = 0.f, s1 = 0.f, s2 = 0.f, s3 = 0.f;
#pragma unroll
        for (int d = 0; d < 64; d += 16) {
            float4 a = *(const float4*)&qj[d];
            float4 b = *(const float4*)&qj[d + 4];
            float4 cc = *(const float4*)&qj[d + 8];
            float4 dd = *(const float4*)&qj[d + 12];
            s0 += qi[d] * a.x + qi[d + 1] * a.y + qi[d + 2] * a.z + qi[d + 3] * a.w;
            s1 += qi[d + 4] * b.x + qi[d + 5] * b.y + qi[d + 6] * b.z + qi[d + 7] * b.w;
            s2 += qi[d + 8] * cc.x + qi[d + 9] * cc.y + qi[d + 10] * cc.z + qi[d + 11] * cc.w;
            s3 += qi[d + 12] * dd.x + qi[d + 13] * dd.y + qi[d + 14] * dd.z + qi[d + 15] * dd.w;
        }
        float s = ((s0 + s1) + (s2 + s3)) * scale;
        srow[(size_t)j * W_FR + w] = s;
        float mn = fmaxf(m, s);
        l = l * __expf(m - mn) + __expf(s - mn);
        m = mn;
    }
    float linv = 1.f / l;

    float oa[64];
#pragma unroll
    for (int d = 0; d < 64; d++) oa[d] = 0.f;

    for (int j = 0; j < 512; j++) {
        float pij = __expf(srow[(size_t)j * W_FR + w] - m) * linv;
        const float* vj = &vs[j * VS];
        const float* qj = &qs[j * QS];
#pragma unroll
        for (int d = 0; d < 32; d += 4) {
            float4 v4 = *(const float4*)&vj[d];
            oa[d]     += pij * v4.x;
            oa[d + 1] += pij * v4.y;
            oa[d + 2] += pij * v4.z;
            oa[d + 3] += pij * v4.w;
        }
#pragma unroll
        for (int d = 32; d < 64; d += 4) {
            float4 v4 = *(const float4*)&qj[d];
            oa[d]     += pij * v4.x;
            oa[d + 1] += pij * v4.y;
            oa[d + 2] += pij * v4.z;
            oa[d + 3] += pij * v4.w;
        }
    }

    float* ob = o + ((size_t)c * F_DIM + (size_t)h * D_HEAD) * W_FR + w;
#pragma unroll
    for (int d = 0; d < 64; d++)
        ob[(size_t)d * W_FR] = oa[d];
}

// ---------------------------------------------------------------------------
// Launch
// ---------------------------------------------------------------------------
extern "C" void kernel_launch(void* const* d_in, const int* in_sizes, int n_in,
                              void* d_out, int out_size)
{
    (void)in_sizes; (void)n_in; (void)out_size;
    const float* x  = (const float*)d_in[0];
    const float* g1 = (const float*)d_in[1];
    const float* b1 = (const float*)d_in[2];
    const float* wq = (const float*)d_in[3];
    const float* wo = (const float*)d_in[4];
    const float* fr = (const float*)d_in[5];
    const float* g2 = (const float*)d_in[6];
    const float* b2 = (const float*)d_in[7];
    const float* w1 = (const float*)d_in[8];
    const float* w2 = (const float*)d_in[9];
    float* out = (float*)d_out;

    float *z, *p, *o, *h, *s;
    cudaGetSymbolAddress((void**)&z, g_z);
    cudaGetSymbolAddress((void**)&p, g_p);
    cudaGetSymbolAddress((void**)&o, g_o);
    cudaGetSymbolAddress((void**)&h, g_h);
    cudaGetSymbolAddress((void**)&s, g_s);

    int smem_attn = 512 * (QS + VS) * (int)sizeof(float);
    cudaFuncSetAttribute(attention_kernel,
                         cudaFuncAttributeMaxDynamicSharedMemorySize, smem_attn);
    cudaFuncSetAttribute(tgemm_kernel,
                         cudaFuncAttributeMaxDynamicSharedMemorySize, GEMM_SMEM_BYTES);

    // z = frame_norm(x)
    frame_norm_kernel<<<dim3(8, 16), 256>>>(x, g1, b1, z);
    // p = w_q @ z
    tgemm_kernel<<<dim3(4, 8, 8), 256, GEMM_SMEM_BYTES>>>(wq, z, p, nullptr, F_DIM, F_DIM, 0);
    // o = attention(p)
    attention_kernel<<<128, 512, smem_attn>>>(p, fr, o, s);
    // x2 = x + w_o @ o   -> d_out
    tgemm_kernel<<<dim3(4, 8, 8), 256, GEMM_SMEM_BYTES>>>(wo, o, out, x, F_DIM, F_DIM, 2);
    // z2 = frame_norm(x2)
    frame_norm_kernel<<<dim3(8, 16), 256>>>(out, g2, b2, z);
    // hgelu = gelu(w1 @ z2)
    tgemm_kernel<<<dim3(4, 32, 8), 256, GEMM_SMEM_BYTES>>>(w1, z, h, nullptr, F4, F_DIM, 1);
    // out = x2 + w2 @ hgelu
    tgemm_kernel<<<dim3(4, 8, 8), 256, GEMM_SMEM_BYTES>>>(w2, h, out, out, F_DIM, F4, 2);
}